// round 4
// baseline (speedup 1.0000x reference)
#include <cuda_runtime.h>
#include <math.h>

#define Bn 32
#define Cn 20
#define Sn 65536
#define Mn 16
#define Qn 4096
#define Hn 128

typedef unsigned long long ull;

// Scratch (device globals; allocation-free rule)
__device__ float  g_h[(size_t)Bn * Cn * Sn];          // (B, C, S) ~168MB
__device__ float  g_partR[Bn][Cn][2][Mn];
__device__ float  g_partI[Bn][Cn][2][Mn];
__device__ float2 g_coef[Bn][Cn][Mn];
__device__ float  g_maxv;

__device__ __forceinline__ float gelu_exact(float x) {
    return 0.5f * x * (1.0f + erff(x * 0.7071067811865476f));
}

// ---------------- packed f32x2 helpers ----------------
__device__ __forceinline__ ull pk2(float x, float y) {
    ull r; asm("mov.b64 %0, {%1, %2};" : "=l"(r) : "f"(x), "f"(y)); return r;
}
__device__ __forceinline__ void upk2(ull a, float& x, float& y) {
    asm("mov.b64 {%0, %1}, %2;" : "=f"(x), "=f"(y) : "l"(a));
}
__device__ __forceinline__ ull f2fma(ull a, ull b, ull c) {
    ull d; asm("fma.rn.f32x2 %0, %1, %2, %3;" : "=l"(d) : "l"(a), "l"(b), "l"(c)); return d;
}
__device__ __forceinline__ ull f2mul(ull a, ull b) {
    ull d; asm("mul.rn.f32x2 %0, %1, %2;" : "=l"(d) : "l"(a), "l"(b)); return d;
}

// ------------------------------------------------------------------ max
__global__ void fno_kmax(const float* __restrict__ p) {
    __shared__ float sm[1024];
    float m = -1e30f;
    for (int i = threadIdx.x; i < Sn; i += 1024) m = fmaxf(m, p[i]);
    sm[threadIdx.x] = m;
    __syncthreads();
    for (int off = 512; off; off >>= 1) {
        if (threadIdx.x < off) sm[threadIdx.x] = fmaxf(sm[threadIdx.x], sm[threadIdx.x + off]);
        __syncthreads();
    }
    if (threadIdx.x == 0) g_maxv = sm[0];
}

// ------------------------------------------------------------------ fc0
__global__ void __launch_bounds__(256) fno_kfc0(const float* __restrict__ x,
                                                const float* __restrict__ p,
                                                const float* __restrict__ w,
                                                const float* __restrict__ bias) {
    const int s = blockIdx.x * 256 + threadIdx.x;
    const int b = blockIdx.y;
    const float xv = x[(size_t)b * Sn + s];
    const float gv = p[s] / g_maxv;
#pragma unroll
    for (int c = 0; c < Cn; c++) {
        g_h[((size_t)(b * Cn + c)) * Sn + s] = fmaf(xv, w[c], fmaf(gv, w[Cn + c], bias[c]));
    }
}

// --------------------------------------------- forward truncated DFT (16 modes)
__global__ void __launch_bounds__(256) fno_kfwd() {
    const int qc = blockIdx.x;   // 0..1
    const int c  = blockIdx.y;   // 0..19
    const int b  = blockIdx.z;   // 0..31
    const float* __restrict__ row = g_h + ((size_t)(b * Cn + c)) * Sn;
    const int tid = threadIdx.x;
    const int q0 = qc * 2048 + tid;

    float Fr[Mn], Fi[Mn];
#pragma unroll
    for (int k = 0; k < Mn; k++) { Fr[k] = 0.f; Fi[k] = 0.f; }

    float zr, zi;
    sincospif(-(float)q0 * (1.0f / 32768.0f), &zi, &zr);
    const float Rr =  0.9996988186962042f;
    const float Ri = -0.0245412285229123f;

    const float C16[16] = { 1.f,  0.9238795325112867f,  0.7071067811865476f,  0.3826834323650898f,
                            0.f, -0.3826834323650898f, -0.7071067811865476f, -0.9238795325112867f,
                           -1.f, -0.9238795325112867f, -0.7071067811865476f, -0.3826834323650898f,
                            0.f,  0.3826834323650898f,  0.7071067811865476f,  0.9238795325112867f };
    const float S16[16] = { 0.f,  0.3826834323650898f,  0.7071067811865476f,  0.9238795325112867f,
                            1.f,  0.9238795325112867f,  0.7071067811865476f,  0.3826834323650898f,
                            0.f, -0.3826834323650898f, -0.7071067811865476f, -0.9238795325112867f,
                           -1.f, -0.9238795325112867f, -0.7071067811865476f, -0.3826834323650898f };

    for (int it = 0; it < 8; ++it) {
        const int q = q0 + it * 256;
        float hp[16];
#pragma unroll
        for (int p = 0; p < 16; p++) hp[p] = row[q + p * Qn];

        float u[8], dd[8];
#pragma unroll
        for (int p = 0; p < 8; p++) { u[p] = hp[p] + hp[p + 8]; dd[p] = hp[p] - hp[p + 8]; }

        float BR[16], BI[16];
#pragma unroll
        for (int j = 0; j <= 4; j++) {
            float ar = 0.f, ai = 0.f;
#pragma unroll
            for (int p = 0; p < 8; p++) {
                const int m = (2 * j * p) & 15;
                ar += u[p] * C16[m];
                ai -= u[p] * S16[m];
            }
            BR[2 * j] = ar; BI[2 * j] = ai;
        }
#pragma unroll
        for (int k = 1; k < 8; k += 2) {
            float ar = 0.f, ai = 0.f;
#pragma unroll
            for (int p = 0; p < 8; p++) {
                const int m = (k * p) & 15;
                ar += dd[p] * C16[m];
                ai -= dd[p] * S16[m];
            }
            BR[k] = ar; BI[k] = ai;
        }
#pragma unroll
        for (int k = 9; k < 16; k++) { BR[k] = BR[16 - k]; BI[k] = -BI[16 - k]; }

        Fr[0] += BR[0];
        Fi[0] += BI[0];
        float wr = zr, wi = zi;
#pragma unroll
        for (int k = 1; k < 16; k++) {
            Fr[k] += BR[k] * wr - BI[k] * wi;
            Fi[k] += BR[k] * wi + BI[k] * wr;
            const float nwr = wr * zr - wi * zi;
            const float nwi = wr * zi + wi * zr;
            wr = nwr; wi = nwi;
        }
        const float nzr = zr * Rr - zi * Ri;
        const float nzi = zr * Ri + zi * Rr;
        zr = nzr; zi = nzi;
    }

#pragma unroll
    for (int off = 16; off; off >>= 1) {
#pragma unroll
        for (int k = 0; k < Mn; k++) {
            Fr[k] += __shfl_down_sync(0xffffffffu, Fr[k], off);
            Fi[k] += __shfl_down_sync(0xffffffffu, Fi[k], off);
        }
    }
    __shared__ float redR[8][Mn], redI[8][Mn];
    const int warp = tid >> 5, lane = tid & 31;
    if (lane == 0) {
#pragma unroll
        for (int k = 0; k < Mn; k++) { redR[warp][k] = Fr[k]; redI[warp][k] = Fi[k]; }
    }
    __syncthreads();
    if (tid < Mn) {
        float ar = 0.f, ai = 0.f;
#pragma unroll
        for (int w = 0; w < 8; w++) { ar += redR[w][tid]; ai += redI[w][tid]; }
        g_partR[b][c][qc][tid] = ar;
        g_partI[b][c][qc][tid] = ai;
    }
}

// ------------------------------------------------------------------ mode mixing
__global__ void fno_kmix(const float* __restrict__ sre, const float* __restrict__ sim) {
    const int b = blockIdx.x;
    const int tid = threadIdx.x;          // 320 threads: o*16 + k
    const int o = tid >> 4, k = tid & 15;
    float Gr = 0.f, Gi = 0.f;
#pragma unroll
    for (int i = 0; i < Cn; i++) {
        const float fr = g_partR[b][i][0][k] + g_partR[b][i][1][k];
        const float fi = g_partI[b][i][0][k] + g_partI[b][i][1][k];
        const float wr = sre[i * (Cn * Mn) + o * Mn + k];
        const float wi = sim[i * (Cn * Mn) + o * Mn + k];
        Gr += fr * wr - fi * wi;
        Gi += fr * wi + fi * wr;
    }
    const float invS = 1.0f / (float)Sn;
    float2 cf;
    if (k == 0) { cf.x = Gr * invS; cf.y = 0.f; }
    else        { cf.x = 2.f * Gr * invS; cf.y = 2.f * Gi * invS; }
    g_coef[b][o][k] = cf;
}

// twiddle rotation between sample s and s+256:  e^{+2pi i * 256/65536}
#define C256 0.9996988186962042f
#define S256 0.0245412285229123f

// -------- packed inverse + 1x1 conv + gelu (layers 0..2), 2 samples/thread ----
__global__ void __launch_bounds__(256) fno_kinv2(const float* __restrict__ ww,
                                                 const float* __restrict__ wb) {
    __shared__ ulonglong2 s_spec[Cn][Mn];    // [o][k]: {dup(cx), dup(-cy)}, k>=1
    __shared__ ull        s_base[Cn];        // dup(coef[o][0].x + wb[o])
    __shared__ ulonglong2 s_ww2[Cn][Cn / 2]; // [o][j]: {dup(w[o][2j]), dup(w[o][2j+1])}
    const int b = blockIdx.y;
    const int tid = threadIdx.x;

    for (int i = tid; i < Cn * Mn; i += 256) {
        const int o = i >> 4, k = i & 15;
        const float2 cf = g_coef[b][o][k];
        if (k == 0) {
            const float v = cf.x + wb[o];
            s_base[o] = pk2(v, v);
        } else {
            s_spec[o][k].x = pk2(cf.x, cf.x);
            s_spec[o][k].y = pk2(-cf.y, -cf.y);
        }
    }
    for (int i = tid; i < Cn * (Cn / 2); i += 256) {
        const int o = i / (Cn / 2), j = i % (Cn / 2);
        const float w0 = ww[o * Cn + 2 * j], w1 = ww[o * Cn + 2 * j + 1];
        s_ww2[o][j].x = pk2(w0, w0);
        s_ww2[o][j].y = pk2(w1, w1);
    }
    __syncthreads();

    const int s0 = blockIdx.x * 512 + tid;   // second sample: s0 + 256
    float co, si;
    sincospif((float)s0 * (1.0f / 32768.0f), &si, &co);
    const float zr1 = co * C256 - si * S256;
    const float zi1 = co * S256 + si * C256;
    ull zr2 = pk2(co, zr1), zi2 = pk2(si, zi1);
    ull nzi2 = pk2(-si, -zi1);
    ull wr2 = zr2, wi2 = zi2;

    ull to2[Cn];
#pragma unroll
    for (int o = 0; o < Cn; o++) to2[o] = s_base[o];

#pragma unroll
    for (int k = 1; k < Mn; k++) {
#pragma unroll
        for (int o = 0; o < Cn; o++) {
            const ulonglong2 sp = s_spec[o][k];
            to2[o] = f2fma(wr2, sp.x, to2[o]);
            to2[o] = f2fma(wi2, sp.y, to2[o]);
        }
        if (k < Mn - 1) {
            const ull nr = f2fma(wi2, nzi2, f2mul(wr2, zr2));
            const ull ni = f2fma(wi2, zr2, f2mul(wr2, zi2));
            wr2 = nr; wi2 = ni;
        }
    }

    ull hv2[Cn];
#pragma unroll
    for (int c = 0; c < Cn; c++) {
        const float* rr = g_h + ((size_t)(b * Cn + c)) * Sn + s0;
        hv2[c] = pk2(rr[0], rr[256]);
    }
#pragma unroll
    for (int o = 0; o < Cn; o++) {
#pragma unroll
        for (int j = 0; j < Cn / 2; j++) {
            const ulonglong2 wv = s_ww2[o][j];
            to2[o] = f2fma(hv2[2 * j], wv.x, to2[o]);
            to2[o] = f2fma(hv2[2 * j + 1], wv.y, to2[o]);
        }
    }
#pragma unroll
    for (int o = 0; o < Cn; o++) {
        float a, bb;
        upk2(to2[o], a, bb);
        float* wrow = g_h + ((size_t)(b * Cn + o)) * Sn + s0;
        wrow[0]   = gelu_exact(a);
        wrow[256] = gelu_exact(bb);
    }
}

// ---- packed final: layer-3 inverse+conv -> fc1 -> gelu -> fc2, 2 samples/thread
__global__ void __launch_bounds__(256) fno_kfinal2(const float* __restrict__ ww,
                                                   const float* __restrict__ wb,
                                                   const float* __restrict__ fc1w,
                                                   const float* __restrict__ fc1b,
                                                   const float* __restrict__ fc2w,
                                                   const float* __restrict__ fc2b,
                                                   float* __restrict__ out) {
    __shared__ ulonglong2 s_spec[Cn][Mn];
    __shared__ ull        s_base[Cn];
    __shared__ ulonglong2 s_ww2[Cn][Cn / 2];
    __shared__ ulonglong2 s_fc1d[Cn][Hn / 2]; // [c][h2]: {dup(w[c][2h2]), dup(w[c][2h2+1])}
    __shared__ ull        s_fc1bd[Hn];        // dup(bias)
    __shared__ ull        s_fc2d[Hn];         // dup(fc2w)
    const int b = blockIdx.y;
    const int tid = threadIdx.x;

    for (int i = tid; i < Cn * Mn; i += 256) {
        const int o = i >> 4, k = i & 15;
        const float2 cf = g_coef[b][o][k];
        if (k == 0) {
            const float v = cf.x + wb[o];
            s_base[o] = pk2(v, v);
        } else {
            s_spec[o][k].x = pk2(cf.x, cf.x);
            s_spec[o][k].y = pk2(-cf.y, -cf.y);
        }
    }
    for (int i = tid; i < Cn * (Cn / 2); i += 256) {
        const int o = i / (Cn / 2), j = i % (Cn / 2);
        const float w0 = ww[o * Cn + 2 * j], w1 = ww[o * Cn + 2 * j + 1];
        s_ww2[o][j].x = pk2(w0, w0);
        s_ww2[o][j].y = pk2(w1, w1);
    }
    for (int i = tid; i < Cn * (Hn / 2); i += 256) {
        const int c = i / (Hn / 2), h2 = i % (Hn / 2);
        const float w0 = fc1w[c * Hn + 2 * h2], w1 = fc1w[c * Hn + 2 * h2 + 1];
        s_fc1d[c][h2].x = pk2(w0, w0);
        s_fc1d[c][h2].y = pk2(w1, w1);
    }
    for (int i = tid; i < Hn; i += 256) {
        s_fc1bd[i] = pk2(fc1b[i], fc1b[i]);
        s_fc2d[i]  = pk2(fc2w[i], fc2w[i]);
    }
    __syncthreads();

    const int s0 = blockIdx.x * 512 + tid;
    float co, si;
    sincospif((float)s0 * (1.0f / 32768.0f), &si, &co);
    const float zr1 = co * C256 - si * S256;
    const float zi1 = co * S256 + si * C256;
    ull zr2 = pk2(co, zr1), zi2 = pk2(si, zi1);
    ull nzi2 = pk2(-si, -zi1);
    ull wr2 = zr2, wi2 = zi2;

    ull to2[Cn];
#pragma unroll
    for (int o = 0; o < Cn; o++) to2[o] = s_base[o];

#pragma unroll
    for (int k = 1; k < Mn; k++) {
#pragma unroll
        for (int o = 0; o < Cn; o++) {
            const ulonglong2 sp = s_spec[o][k];
            to2[o] = f2fma(wr2, sp.x, to2[o]);
            to2[o] = f2fma(wi2, sp.y, to2[o]);
        }
        if (k < Mn - 1) {
            const ull nr = f2fma(wi2, nzi2, f2mul(wr2, zr2));
            const ull ni = f2fma(wi2, zr2, f2mul(wr2, zi2));
            wr2 = nr; wi2 = ni;
        }
    }
    {
        ull hv2[Cn];
#pragma unroll
        for (int c = 0; c < Cn; c++) {
            const float* rr = g_h + ((size_t)(b * Cn + c)) * Sn + s0;
            hv2[c] = pk2(rr[0], rr[256]);
        }
#pragma unroll
        for (int o = 0; o < Cn; o++) {
#pragma unroll
            for (int j = 0; j < Cn / 2; j++) {
                const ulonglong2 wv = s_ww2[o][j];
                to2[o] = f2fma(hv2[2 * j], wv.x, to2[o]);
                to2[o] = f2fma(hv2[2 * j + 1], wv.y, to2[o]);
            }
        }
    }
    // to2 = layer-3 output (no gelu). fc1 -> gelu -> fc2, packed over samples.
    const float f2b = fc2b[0];
    ull res2 = pk2(f2b, f2b);
#pragma unroll 2
    for (int h2 = 0; h2 < Hn / 2; h2++) {
        ull a0 = s_fc1bd[2 * h2];
        ull a1 = s_fc1bd[2 * h2 + 1];
#pragma unroll
        for (int c = 0; c < Cn; c++) {
            const ulonglong2 wv = s_fc1d[c][h2];
            a0 = f2fma(to2[c], wv.x, a0);
            a1 = f2fma(to2[c], wv.y, a1);
        }
        float x0, y0, x1, y1;
        upk2(a0, x0, y0);
        upk2(a1, x1, y1);
        const ull g0 = pk2(gelu_exact(x0), gelu_exact(y0));
        const ull g1 = pk2(gelu_exact(x1), gelu_exact(y1));
        res2 = f2fma(g0, s_fc2d[2 * h2], res2);
        res2 = f2fma(g1, s_fc2d[2 * h2 + 1], res2);
    }
    float r0, r1;
    upk2(res2, r0, r1);
    out[(size_t)b * Sn + s0]       = r0;
    out[(size_t)b * Sn + s0 + 256] = r1;
}

// ------------------------------------------------------------------ launch
extern "C" void kernel_launch(void* const* d_in, const int* in_sizes, int n_in,
                              void* d_out, int out_size) {
    const float* x  = (const float*)d_in[0];
    const float* pd = (const float*)d_in[1];
    const float* fc0w = (const float*)d_in[2];
    const float* fc0b = (const float*)d_in[3];
    const float *fc1w, *fc1b, *fc2w, *fc2b;
    const float *sre[4], *sim[4], *lww[4], *lwb[4];

    if (in_sizes[4] == Cn * Hn) {
        fc1w = (const float*)d_in[4]; fc1b = (const float*)d_in[5];
        fc2w = (const float*)d_in[6]; fc2b = (const float*)d_in[7];
        for (int l = 0; l < 4; l++) {
            sre[l] = (const float*)d_in[8 + 4 * l];
            sim[l] = (const float*)d_in[9 + 4 * l];
            lww[l] = (const float*)d_in[10 + 4 * l];
            lwb[l] = (const float*)d_in[11 + 4 * l];
        }
    } else {
        for (int l = 0; l < 4; l++) {
            sre[l] = (const float*)d_in[4 + 4 * l];
            sim[l] = (const float*)d_in[5 + 4 * l];
            lww[l] = (const float*)d_in[6 + 4 * l];
            lwb[l] = (const float*)d_in[7 + 4 * l];
        }
        fc1w = (const float*)d_in[20]; fc1b = (const float*)d_in[21];
        fc2w = (const float*)d_in[22]; fc2b = (const float*)d_in[23];
    }

    float* out = (float*)d_out;

    fno_kmax<<<1, 1024>>>(pd);
    fno_kfc0<<<dim3(Sn / 256, Bn), 256>>>(x, pd, fc0w, fc0b);

    for (int l = 0; l < 3; l++) {
        fno_kfwd<<<dim3(2, Cn, Bn), 256>>>();
        fno_kmix<<<Bn, Cn * Mn>>>(sre[l], sim[l]);
        fno_kinv2<<<dim3(Sn / 512, Bn), 256>>>(lww[l], lwb[l]);
    }
    fno_kfwd<<<dim3(2, Cn, Bn), 256>>>();
    fno_kmix<<<Bn, Cn * Mn>>>(sre[3], sim[3]);
    fno_kfinal2<<<dim3(Sn / 512, Bn), 256>>>(lww[3], lwb[3], fc1w, fc1b, fc2w, fc2b, out);
}

// round 5
// speedup vs baseline: 1.3600x; 1.3600x over previous
#include <cuda_runtime.h>
#include <math.h>

#define Bn 32
#define Cn 20
#define Sn 65536
#define Mn 16
#define Qn 4096
#define Hn 128

// Scratch (device globals; allocation-free rule)
__device__ float  g_h[(size_t)Bn * Cn * Sn];          // (B, C, S) ~168MB
__device__ float  g_partR[Bn][Cn][2][Mn];
__device__ float  g_partI[Bn][Cn][2][Mn];
__device__ float2 g_coef[Bn][Cn][Mn];
__device__ float  g_maxv;

// Fast gelu: A&S 7.1.28 erf approximation, |eps| <= 3e-7, branch-free.
// erf(u) ~= 1 - (1 + a1 u + ... + a6 u^6)^-16  for u >= 0.
__device__ __forceinline__ float fast_rcp(float x) {
    float r; asm("rcp.approx.f32 %0, %1;" : "=f"(r) : "f"(x)); return r;
}
__device__ __forceinline__ float gelu_fast(float x) {
    const float u = fabsf(x) * 0.7071067811865476f;
    float p = fmaf(0.0000430638f, u, 0.0002765672f);
    p = fmaf(p, u, 0.0001520143f);
    p = fmaf(p, u, 0.0092705272f);
    p = fmaf(p, u, 0.0422820123f);
    p = fmaf(p, u, 0.0705230784f);
    p = fmaf(p, u, 1.0f);
    float r = fast_rcp(p);
    r = r * r; r = r * r; r = r * r; r = r * r;   // ^16
    const float erf_abs = 1.0f - r;
    const float erf_v = copysignf(erf_abs, x);
    return 0.5f * x * (1.0f + erf_v);
}

// ------------------------------------------------------------------ max
__global__ void fno_kmax(const float* __restrict__ p) {
    __shared__ float sm[1024];
    float m = -1e30f;
    for (int i = threadIdx.x; i < Sn; i += 1024) m = fmaxf(m, p[i]);
    sm[threadIdx.x] = m;
    __syncthreads();
    for (int off = 512; off; off >>= 1) {
        if (threadIdx.x < off) sm[threadIdx.x] = fmaxf(sm[threadIdx.x], sm[threadIdx.x + off]);
        __syncthreads();
    }
    if (threadIdx.x == 0) g_maxv = sm[0];
}

// ------------------------------------------------------------------ fc0
__global__ void __launch_bounds__(256) fno_kfc0(const float* __restrict__ x,
                                                const float* __restrict__ p,
                                                const float* __restrict__ w,
                                                const float* __restrict__ bias) {
    const int s = blockIdx.x * 256 + threadIdx.x;
    const int b = blockIdx.y;
    const float xv = x[(size_t)b * Sn + s];
    const float gv = p[s] / g_maxv;
#pragma unroll
    for (int c = 0; c < Cn; c++) {
        g_h[((size_t)(b * Cn + c)) * Sn + s] = fmaf(xv, w[c], fmaf(gv, w[Cn + c], bias[c]));
    }
}

// --------------------------------------------- forward truncated DFT (16 modes)
__global__ void __launch_bounds__(256) fno_kfwd() {
    const int qc = blockIdx.x;   // 0..1
    const int c  = blockIdx.y;   // 0..19
    const int b  = blockIdx.z;   // 0..31
    const float* __restrict__ row = g_h + ((size_t)(b * Cn + c)) * Sn;
    const int tid = threadIdx.x;
    const int q0 = qc * 2048 + tid;

    float Fr[Mn], Fi[Mn];
#pragma unroll
    for (int k = 0; k < Mn; k++) { Fr[k] = 0.f; Fi[k] = 0.f; }

    float zr, zi;
    sincospif(-(float)q0 * (1.0f / 32768.0f), &zi, &zr);
    const float Rr =  0.9996988186962042f;
    const float Ri = -0.0245412285229123f;

    const float C16[16] = { 1.f,  0.9238795325112867f,  0.7071067811865476f,  0.3826834323650898f,
                            0.f, -0.3826834323650898f, -0.7071067811865476f, -0.9238795325112867f,
                           -1.f, -0.9238795325112867f, -0.7071067811865476f, -0.3826834323650898f,
                            0.f,  0.3826834323650898f,  0.7071067811865476f,  0.9238795325112867f };
    const float S16[16] = { 0.f,  0.3826834323650898f,  0.7071067811865476f,  0.9238795325112867f,
                            1.f,  0.9238795325112867f,  0.7071067811865476f,  0.3826834323650898f,
                            0.f, -0.3826834323650898f, -0.7071067811865476f, -0.9238795325112867f,
                           -1.f, -0.9238795325112867f, -0.7071067811865476f, -0.3826834323650898f };

    for (int it = 0; it < 8; ++it) {
        const int q = q0 + it * 256;
        float hp[16];
#pragma unroll
        for (int p = 0; p < 16; p++) hp[p] = row[q + p * Qn];

        float u[8], dd[8];
#pragma unroll
        for (int p = 0; p < 8; p++) { u[p] = hp[p] + hp[p + 8]; dd[p] = hp[p] - hp[p + 8]; }

        float BR[16], BI[16];
#pragma unroll
        for (int j = 0; j <= 4; j++) {
            float ar = 0.f, ai = 0.f;
#pragma unroll
            for (int p = 0; p < 8; p++) {
                const int m = (2 * j * p) & 15;
                ar += u[p] * C16[m];
                ai -= u[p] * S16[m];
            }
            BR[2 * j] = ar; BI[2 * j] = ai;
        }
#pragma unroll
        for (int k = 1; k < 8; k += 2) {
            float ar = 0.f, ai = 0.f;
#pragma unroll
            for (int p = 0; p < 8; p++) {
                const int m = (k * p) & 15;
                ar += dd[p] * C16[m];
                ai -= dd[p] * S16[m];
            }
            BR[k] = ar; BI[k] = ai;
        }
#pragma unroll
        for (int k = 9; k < 16; k++) { BR[k] = BR[16 - k]; BI[k] = -BI[16 - k]; }

        Fr[0] += BR[0];
        Fi[0] += BI[0];
        float wr = zr, wi = zi;
#pragma unroll
        for (int k = 1; k < 16; k++) {
            Fr[k] += BR[k] * wr - BI[k] * wi;
            Fi[k] += BR[k] * wi + BI[k] * wr;
            const float nwr = wr * zr - wi * zi;
            const float nwi = wr * zi + wi * zr;
            wr = nwr; wi = nwi;
        }
        const float nzr = zr * Rr - zi * Ri;
        const float nzi = zr * Ri + zi * Rr;
        zr = nzr; zi = nzi;
    }

#pragma unroll
    for (int off = 16; off; off >>= 1) {
#pragma unroll
        for (int k = 0; k < Mn; k++) {
            Fr[k] += __shfl_down_sync(0xffffffffu, Fr[k], off);
            Fi[k] += __shfl_down_sync(0xffffffffu, Fi[k], off);
        }
    }
    __shared__ float redR[8][Mn], redI[8][Mn];
    const int warp = tid >> 5, lane = tid & 31;
    if (lane == 0) {
#pragma unroll
        for (int k = 0; k < Mn; k++) { redR[warp][k] = Fr[k]; redI[warp][k] = Fi[k]; }
    }
    __syncthreads();
    if (tid < Mn) {
        float ar = 0.f, ai = 0.f;
#pragma unroll
        for (int w = 0; w < 8; w++) { ar += redR[w][tid]; ai += redI[w][tid]; }
        g_partR[b][c][qc][tid] = ar;
        g_partI[b][c][qc][tid] = ai;
    }
}

// ------------------------------------------------------------------ mode mixing
__global__ void fno_kmix(const float* __restrict__ sre, const float* __restrict__ sim) {
    const int b = blockIdx.x;
    const int tid = threadIdx.x;          // 320 threads: o*16 + k
    const int o = tid >> 4, k = tid & 15;
    float Gr = 0.f, Gi = 0.f;
#pragma unroll
    for (int i = 0; i < Cn; i++) {
        const float fr = g_partR[b][i][0][k] + g_partR[b][i][1][k];
        const float fi = g_partI[b][i][0][k] + g_partI[b][i][1][k];
        const float wr = sre[i * (Cn * Mn) + o * Mn + k];
        const float wi = sim[i * (Cn * Mn) + o * Mn + k];
        Gr += fr * wr - fi * wi;
        Gi += fr * wi + fi * wr;
    }
    const float invS = 1.0f / (float)Sn;
    float2 cf;
    if (k == 0) { cf.x = Gr * invS; cf.y = 0.f; }
    else        { cf.x = 2.f * Gr * invS; cf.y = 2.f * Gi * invS; }
    g_coef[b][o][k] = cf;
}

// ------------------------------------- inverse + 1x1 conv + gelu (layers 0..2)
__global__ void __launch_bounds__(256) fno_kinv(const float* __restrict__ ww,
                                                const float* __restrict__ wb) {
    __shared__ float2 s_coef[Cn][Mn];
    __shared__ float  s_ww[Cn * Cn];
    __shared__ float  s_wb[Cn];
    const int b = blockIdx.y;
    const int tid = threadIdx.x;
    for (int i = tid; i < Cn * Mn; i += 256) s_coef[i / Mn][i % Mn] = g_coef[b][i / Mn][i % Mn];
    for (int i = tid; i < Cn * Cn; i += 256) s_ww[i] = ww[i];
    if (tid < Cn) s_wb[tid] = wb[tid];
    __syncthreads();

    const int s = blockIdx.x * 256 + tid;
    float co, si;
    sincospif((float)s * (1.0f / 32768.0f), &si, &co);   // e^{+2pi i s/S}
    float cs[Mn], sn[Mn];
    {
        float wr = co, wi = si;
#pragma unroll
        for (int k = 1; k < Mn; k++) {
            cs[k] = wr; sn[k] = wi;
            const float nr = wr * co - wi * si;
            const float ni = wr * si + wi * co;
            wr = nr; wi = ni;
        }
    }
    float hv[Cn];
#pragma unroll
    for (int c = 0; c < Cn; c++) hv[c] = g_h[((size_t)(b * Cn + c)) * Sn + s];

    float outv[Cn];
#pragma unroll
    for (int o = 0; o < Cn; o++) {
        float acc = s_coef[o][0].x + s_wb[o];
#pragma unroll
        for (int k = 1; k < Mn; k++) {
            const float2 cc = s_coef[o][k];
            acc += cc.x * cs[k] - cc.y * sn[k];
        }
#pragma unroll
        for (int c = 0; c < Cn; c++) acc += hv[c] * s_ww[o * Cn + c];
        outv[o] = gelu_fast(acc);
    }
#pragma unroll
    for (int o = 0; o < Cn; o++) g_h[((size_t)(b * Cn + o)) * Sn + s] = outv[o];
}

// ---------- final: layer-3 inverse+conv (no gelu) -> fc1 -> gelu -> fc2 -------
__global__ void __launch_bounds__(256) fno_kfinal(const float* __restrict__ ww,
                                                  const float* __restrict__ wb,
                                                  const float* __restrict__ fc1w,
                                                  const float* __restrict__ fc1b,
                                                  const float* __restrict__ fc2w,
                                                  const float* __restrict__ fc2b,
                                                  float* __restrict__ out) {
    __shared__ float2 s_coef[Cn][Mn];
    __shared__ float  s_ww[Cn * Cn];
    __shared__ float  s_wb[Cn];
    __shared__ float4 s_fc1[Cn][Hn / 4];
    __shared__ float4 s_fc1b[Hn / 4];
    __shared__ float4 s_fc2[Hn / 4];
    const int b = blockIdx.y;
    const int tid = threadIdx.x;
    for (int i = tid; i < Cn * Mn; i += 256) s_coef[i / Mn][i % Mn] = g_coef[b][i / Mn][i % Mn];
    for (int i = tid; i < Cn * Cn; i += 256) s_ww[i] = ww[i];
    if (tid < Cn) s_wb[tid] = wb[tid];
    for (int i = tid; i < Cn * (Hn / 4); i += 256) {
        const int c = i / (Hn / 4), h4 = i % (Hn / 4);
        s_fc1[c][h4] = make_float4(fc1w[c * Hn + 4 * h4 + 0], fc1w[c * Hn + 4 * h4 + 1],
                                   fc1w[c * Hn + 4 * h4 + 2], fc1w[c * Hn + 4 * h4 + 3]);
    }
    if (tid < Hn / 4) {
        s_fc1b[tid] = make_float4(fc1b[4 * tid], fc1b[4 * tid + 1], fc1b[4 * tid + 2], fc1b[4 * tid + 3]);
        s_fc2[tid]  = make_float4(fc2w[4 * tid], fc2w[4 * tid + 1], fc2w[4 * tid + 2], fc2w[4 * tid + 3]);
    }
    __syncthreads();

    const int s = blockIdx.x * 256 + tid;
    float co, si;
    sincospif((float)s * (1.0f / 32768.0f), &si, &co);
    float cs[Mn], sn[Mn];
    {
        float wr = co, wi = si;
#pragma unroll
        for (int k = 1; k < Mn; k++) {
            cs[k] = wr; sn[k] = wi;
            const float nr = wr * co - wi * si;
            const float ni = wr * si + wi * co;
            wr = nr; wi = ni;
        }
    }
    float t[Cn];
#pragma unroll
    for (int c = 0; c < Cn; c++) t[c] = g_h[((size_t)(b * Cn + c)) * Sn + s];

    float to[Cn];
#pragma unroll
    for (int o = 0; o < Cn; o++) {
        float acc = s_coef[o][0].x + s_wb[o];
#pragma unroll
        for (int k = 1; k < Mn; k++) {
            const float2 cc = s_coef[o][k];
            acc += cc.x * cs[k] - cc.y * sn[k];
        }
#pragma unroll
        for (int c = 0; c < Cn; c++) acc += t[c] * s_ww[o * Cn + c];
        to[o] = acc;                       // layer 3: NO gelu
    }

    float res = fc2b[0];
#pragma unroll 4
    for (int h4 = 0; h4 < Hn / 4; h4++) {
        float4 a = s_fc1b[h4];
#pragma unroll
        for (int c = 0; c < Cn; c++) {
            const float4 w4 = s_fc1[c][h4];
            a.x = fmaf(to[c], w4.x, a.x);
            a.y = fmaf(to[c], w4.y, a.y);
            a.z = fmaf(to[c], w4.z, a.z);
            a.w = fmaf(to[c], w4.w, a.w);
        }
        const float4 f2 = s_fc2[h4];
        res += gelu_fast(a.x) * f2.x + gelu_fast(a.y) * f2.y
             + gelu_fast(a.z) * f2.z + gelu_fast(a.w) * f2.w;
    }
    out[(size_t)b * Sn + s] = res;
}

// ------------------------------------------------------------------ launch
extern "C" void kernel_launch(void* const* d_in, const int* in_sizes, int n_in,
                              void* d_out, int out_size) {
    const float* x  = (const float*)d_in[0];
    const float* pd = (const float*)d_in[1];
    const float* fc0w = (const float*)d_in[2];
    const float* fc0b = (const float*)d_in[3];
    const float *fc1w, *fc1b, *fc2w, *fc2b;
    const float *sre[4], *sim[4], *lww[4], *lwb[4];

    if (in_sizes[4] == Cn * Hn) {
        fc1w = (const float*)d_in[4]; fc1b = (const float*)d_in[5];
        fc2w = (const float*)d_in[6]; fc2b = (const float*)d_in[7];
        for (int l = 0; l < 4; l++) {
            sre[l] = (const float*)d_in[8 + 4 * l];
            sim[l] = (const float*)d_in[9 + 4 * l];
            lww[l] = (const float*)d_in[10 + 4 * l];
            lwb[l] = (const float*)d_in[11 + 4 * l];
        }
    } else {
        for (int l = 0; l < 4; l++) {
            sre[l] = (const float*)d_in[4 + 4 * l];
            sim[l] = (const float*)d_in[5 + 4 * l];
            lww[l] = (const float*)d_in[6 + 4 * l];
            lwb[l] = (const float*)d_in[7 + 4 * l];
        }
        fc1w = (const float*)d_in[20]; fc1b = (const float*)d_in[21];
        fc2w = (const float*)d_in[22]; fc2b = (const float*)d_in[23];
    }

    float* out = (float*)d_out;
    const dim3 gS(Sn / 256, Bn);

    fno_kmax<<<1, 1024>>>(pd);
    fno_kfc0<<<gS, 256>>>(x, pd, fc0w, fc0b);

    for (int l = 0; l < 3; l++) {
        fno_kfwd<<<dim3(2, Cn, Bn), 256>>>();
        fno_kmix<<<Bn, Cn * Mn>>>(sre[l], sim[l]);
        fno_kinv<<<gS, 256>>>(lww[l], lwb[l]);
    }
    fno_kfwd<<<dim3(2, Cn, Bn), 256>>>();
    fno_kmix<<<Bn, Cn * Mn>>>(sre[3], sim[3]);
    fno_kfinal<<<gS, 256>>>(lww[3], lwb[3], fc1w, fc1b, fc2w, fc2b, out);
}

// round 6
// speedup vs baseline: 1.7168x; 1.2623x over previous
#include <cuda_runtime.h>
#include <math.h>

#define Bn 32
#define Cn 20
#define Sn 65536
#define Mn 16
#define Qn 4096
#define Hn 128

// Scratch (device globals; allocation-free rule)
__device__ float  g_h[(size_t)Bn * Cn * Sn];          // (B, C, S) ~168MB
__device__ float  g_partR[Bn][Cn][2][Mn];
__device__ float  g_partI[Bn][Cn][2][Mn];
__device__ float2 g_coef[Bn][Cn][Mn];
__device__ float  g_maxv;

// Fast gelu: A&S 7.1.28 erf approximation, |eps| <= 3e-7, branch-free.
__device__ __forceinline__ float fast_rcp(float x) {
    float r; asm("rcp.approx.f32 %0, %1;" : "=f"(r) : "f"(x)); return r;
}
__device__ __forceinline__ float gelu_fast(float x) {
    const float u = fabsf(x) * 0.7071067811865476f;
    float p = fmaf(0.0000430638f, u, 0.0002765672f);
    p = fmaf(p, u, 0.0001520143f);
    p = fmaf(p, u, 0.0092705272f);
    p = fmaf(p, u, 0.0422820123f);
    p = fmaf(p, u, 0.0705230784f);
    p = fmaf(p, u, 1.0f);
    float r = fast_rcp(p);
    r = r * r; r = r * r; r = r * r; r = r * r;   // ^16
    const float erf_v = copysignf(1.0f - r, x);
    return 0.5f * x * (1.0f + erf_v);
}

// rotation between sample s and s+1: e^{+2pi i/65536}
#define C1R 0.9999999954025773f
#define S1R 9.587379909597734e-5f

// ------------------------------------------------------------------ max
__global__ void fno_kmax(const float* __restrict__ p) {
    __shared__ float sm[1024];
    float m = -1e30f;
    for (int i = threadIdx.x; i < Sn; i += 1024) m = fmaxf(m, p[i]);
    sm[threadIdx.x] = m;
    __syncthreads();
    for (int off = 512; off; off >>= 1) {
        if (threadIdx.x < off) sm[threadIdx.x] = fmaxf(sm[threadIdx.x], sm[threadIdx.x + off]);
        __syncthreads();
    }
    if (threadIdx.x == 0) g_maxv = sm[0];
}

// ------------------------------------------------------------------ fc0
__global__ void __launch_bounds__(256) fno_kfc0(const float* __restrict__ x,
                                                const float* __restrict__ p,
                                                const float* __restrict__ w,
                                                const float* __restrict__ bias) {
    const int s = blockIdx.x * 256 + threadIdx.x;
    const int b = blockIdx.y;
    const float xv = x[(size_t)b * Sn + s];
    const float gv = p[s] / g_maxv;
#pragma unroll
    for (int c = 0; c < Cn; c++) {
        g_h[((size_t)(b * Cn + c)) * Sn + s] = fmaf(xv, w[c], fmaf(gv, w[Cn + c], bias[c]));
    }
}

// --------------------------------------------- forward truncated DFT (16 modes)
__global__ void __launch_bounds__(256) fno_kfwd() {
    const int qc = blockIdx.x;   // 0..1
    const int c  = blockIdx.y;   // 0..19
    const int b  = blockIdx.z;   // 0..31
    const float* __restrict__ row = g_h + ((size_t)(b * Cn + c)) * Sn;
    const int tid = threadIdx.x;
    const int q0 = qc * 2048 + tid;

    float Fr[Mn], Fi[Mn];
#pragma unroll
    for (int k = 0; k < Mn; k++) { Fr[k] = 0.f; Fi[k] = 0.f; }

    float zr, zi;
    sincospif(-(float)q0 * (1.0f / 32768.0f), &zi, &zr);
    const float Rr =  0.9996988186962042f;
    const float Ri = -0.0245412285229123f;

    const float C16[16] = { 1.f,  0.9238795325112867f,  0.7071067811865476f,  0.3826834323650898f,
                            0.f, -0.3826834323650898f, -0.7071067811865476f, -0.9238795325112867f,
                           -1.f, -0.9238795325112867f, -0.7071067811865476f, -0.3826834323650898f,
                            0.f,  0.3826834323650898f,  0.7071067811865476f,  0.9238795325112867f };
    const float S16[16] = { 0.f,  0.3826834323650898f,  0.7071067811865476f,  0.9238795325112867f,
                            1.f,  0.9238795325112867f,  0.7071067811865476f,  0.3826834323650898f,
                            0.f, -0.3826834323650898f, -0.7071067811865476f, -0.9238795325112867f,
                           -1.f, -0.9238795325112867f, -0.7071067811865476f, -0.3826834323650898f };

    for (int it = 0; it < 8; ++it) {
        const int q = q0 + it * 256;
        float hp[16];
#pragma unroll
        for (int p = 0; p < 16; p++) hp[p] = row[q + p * Qn];

        float u[8], dd[8];
#pragma unroll
        for (int p = 0; p < 8; p++) { u[p] = hp[p] + hp[p + 8]; dd[p] = hp[p] - hp[p + 8]; }

        float BR[16], BI[16];
#pragma unroll
        for (int j = 0; j <= 4; j++) {
            float ar = 0.f, ai = 0.f;
#pragma unroll
            for (int p = 0; p < 8; p++) {
                const int m = (2 * j * p) & 15;
                ar += u[p] * C16[m];
                ai -= u[p] * S16[m];
            }
            BR[2 * j] = ar; BI[2 * j] = ai;
        }
#pragma unroll
        for (int k = 1; k < 8; k += 2) {
            float ar = 0.f, ai = 0.f;
#pragma unroll
            for (int p = 0; p < 8; p++) {
                const int m = (k * p) & 15;
                ar += dd[p] * C16[m];
                ai -= dd[p] * S16[m];
            }
            BR[k] = ar; BI[k] = ai;
        }
#pragma unroll
        for (int k = 9; k < 16; k++) { BR[k] = BR[16 - k]; BI[k] = -BI[16 - k]; }

        Fr[0] += BR[0];
        Fi[0] += BI[0];
        float wr = zr, wi = zi;
#pragma unroll
        for (int k = 1; k < 16; k++) {
            Fr[k] += BR[k] * wr - BI[k] * wi;
            Fi[k] += BR[k] * wi + BI[k] * wr;
            const float nwr = wr * zr - wi * zi;
            const float nwi = wr * zi + wi * zr;
            wr = nwr; wi = nwi;
        }
        const float nzr = zr * Rr - zi * Ri;
        const float nzi = zr * Ri + zi * Rr;
        zr = nzr; zi = nzi;
    }

#pragma unroll
    for (int off = 16; off; off >>= 1) {
#pragma unroll
        for (int k = 0; k < Mn; k++) {
            Fr[k] += __shfl_down_sync(0xffffffffu, Fr[k], off);
            Fi[k] += __shfl_down_sync(0xffffffffu, Fi[k], off);
        }
    }
    __shared__ float redR[8][Mn], redI[8][Mn];
    const int warp = tid >> 5, lane = tid & 31;
    if (lane == 0) {
#pragma unroll
        for (int k = 0; k < Mn; k++) { redR[warp][k] = Fr[k]; redI[warp][k] = Fi[k]; }
    }
    __syncthreads();
    if (tid < Mn) {
        float ar = 0.f, ai = 0.f;
#pragma unroll
        for (int w = 0; w < 8; w++) { ar += redR[w][tid]; ai += redI[w][tid]; }
        g_partR[b][c][qc][tid] = ar;
        g_partI[b][c][qc][tid] = ai;
    }
}

// ------------------------------------------------------------------ mode mixing
__global__ void fno_kmix(const float* __restrict__ sre, const float* __restrict__ sim) {
    const int b = blockIdx.x;
    const int tid = threadIdx.x;          // 320 threads: o*16 + k
    const int o = tid >> 4, k = tid & 15;
    float Gr = 0.f, Gi = 0.f;
#pragma unroll
    for (int i = 0; i < Cn; i++) {
        const float fr = g_partR[b][i][0][k] + g_partR[b][i][1][k];
        const float fi = g_partI[b][i][0][k] + g_partI[b][i][1][k];
        const float wr = sre[i * (Cn * Mn) + o * Mn + k];
        const float wi = sim[i * (Cn * Mn) + o * Mn + k];
        Gr += fr * wr - fi * wi;
        Gi += fr * wi + fi * wr;
    }
    const float invS = 1.0f / (float)Sn;
    float2 cf;
    if (k == 0) { cf.x = Gr * invS; cf.y = 0.f; }
    else        { cf.x = 2.f * Gr * invS; cf.y = 2.f * Gi * invS; }
    g_coef[b][o][k] = cf;
}

// ---------- inverse + 1x1 conv + gelu (layers 0..2), 2 adjacent samples/thread
__global__ void __launch_bounds__(256) fno_kinv2(const float* __restrict__ ww,
                                                 const float* __restrict__ wb) {
    __shared__ float2 s_spec[Mn][Cn];   // [k][o] = {cx, -cy}, k>=1
    __shared__ float  s_base[Cn];       // coef[o][0].x + wb[o]
    __shared__ float  s_ww[Cn * Cn];    // w[o][c] at o*Cn+c
    const int b = blockIdx.y;
    const int tid = threadIdx.x;

    for (int i = tid; i < Cn * Mn; i += 256) {
        const int o = i >> 4, k = i & 15;
        const float2 cf = g_coef[b][o][k];
        if (k == 0) s_base[o] = cf.x + wb[o];
        else        s_spec[k][o] = make_float2(cf.x, -cf.y);
    }
    for (int i = tid; i < Cn * Cn; i += 256) s_ww[i] = ww[i];
    __syncthreads();

    const int s0 = blockIdx.x * 512 + 2 * tid;   // pair (s0, s0+1)
    float e0r, e0i;
    sincospif((float)s0 * (1.0f / 32768.0f), &e0i, &e0r);  // e^{+2pi i s0/S}
    const float e1r = e0r * C1R - e0i * S1R;
    const float e1i = e0r * S1R + e0i * C1R;

    float to0[Cn], to1[Cn];
#pragma unroll
    for (int o = 0; o < Cn; o++) { to0[o] = s_base[o]; to1[o] = s_base[o]; }

    float w0r = e0r, w0i = e0i, w1r = e1r, w1i = e1i;
#pragma unroll
    for (int k = 1; k < Mn; k++) {
#pragma unroll
        for (int o = 0; o < Cn; o++) {
            const float2 cc = s_spec[k][o];
            to0[o] = fmaf(cc.x, w0r, fmaf(cc.y, w0i, to0[o]));
            to1[o] = fmaf(cc.x, w1r, fmaf(cc.y, w1i, to1[o]));
        }
        if (k < Mn - 1) {
            float nr = w0r * e0r - w0i * e0i, ni = w0r * e0i + w0i * e0r;
            w0r = nr; w0i = ni;
            nr = w1r * e1r - w1i * e1i; ni = w1r * e1i + w1i * e1r;
            w1r = nr; w1i = ni;
        }
    }

    // 1x1 conv: one float2 load per input channel feeds both samples
#pragma unroll
    for (int c = 0; c < Cn; c++) {
        const float2 hp = *(const float2*)(g_h + ((size_t)(b * Cn + c)) * Sn + s0);
#pragma unroll
        for (int o = 0; o < Cn; o++) {
            const float wv = s_ww[o * Cn + c];
            to0[o] = fmaf(hp.x, wv, to0[o]);
            to1[o] = fmaf(hp.y, wv, to1[o]);
        }
    }
#pragma unroll
    for (int o = 0; o < Cn; o++) {
        float2 r = make_float2(gelu_fast(to0[o]), gelu_fast(to1[o]));
        *(float2*)(g_h + ((size_t)(b * Cn + o)) * Sn + s0) = r;
    }
}

// ---- final: layer-3 inverse+conv (no gelu) -> fc1 -> gelu -> fc2, 2 samples/thread
__global__ void __launch_bounds__(256) fno_kfinal2(const float* __restrict__ ww,
                                                   const float* __restrict__ wb,
                                                   const float* __restrict__ fc1w,
                                                   const float* __restrict__ fc1b,
                                                   const float* __restrict__ fc2w,
                                                   const float* __restrict__ fc2b,
                                                   float* __restrict__ out) {
    __shared__ float2 s_spec[Mn][Cn];
    __shared__ float  s_base[Cn];
    __shared__ float  s_ww[Cn * Cn];
    __shared__ float4 s_fc1[Cn][Hn / 4];
    __shared__ float4 s_fc1b[Hn / 4];
    __shared__ float4 s_fc2[Hn / 4];
    const int b = blockIdx.y;
    const int tid = threadIdx.x;

    for (int i = tid; i < Cn * Mn; i += 256) {
        const int o = i >> 4, k = i & 15;
        const float2 cf = g_coef[b][o][k];
        if (k == 0) s_base[o] = cf.x + wb[o];
        else        s_spec[k][o] = make_float2(cf.x, -cf.y);
    }
    for (int i = tid; i < Cn * Cn; i += 256) s_ww[i] = ww[i];
    for (int i = tid; i < Cn * (Hn / 4); i += 256) {
        const int c = i / (Hn / 4), h4 = i % (Hn / 4);
        s_fc1[c][h4] = make_float4(fc1w[c * Hn + 4 * h4 + 0], fc1w[c * Hn + 4 * h4 + 1],
                                   fc1w[c * Hn + 4 * h4 + 2], fc1w[c * Hn + 4 * h4 + 3]);
    }
    if (tid < Hn / 4) {
        s_fc1b[tid] = make_float4(fc1b[4 * tid], fc1b[4 * tid + 1], fc1b[4 * tid + 2], fc1b[4 * tid + 3]);
        s_fc2[tid]  = make_float4(fc2w[4 * tid], fc2w[4 * tid + 1], fc2w[4 * tid + 2], fc2w[4 * tid + 3]);
    }
    __syncthreads();

    const int s0 = blockIdx.x * 512 + 2 * tid;
    float e0r, e0i;
    sincospif((float)s0 * (1.0f / 32768.0f), &e0i, &e0r);
    const float e1r = e0r * C1R - e0i * S1R;
    const float e1i = e0r * S1R + e0i * C1R;

    float to0[Cn], to1[Cn];
#pragma unroll
    for (int o = 0; o < Cn; o++) { to0[o] = s_base[o]; to1[o] = s_base[o]; }

    float w0r = e0r, w0i = e0i, w1r = e1r, w1i = e1i;
#pragma unroll
    for (int k = 1; k < Mn; k++) {
#pragma unroll
        for (int o = 0; o < Cn; o++) {
            const float2 cc = s_spec[k][o];
            to0[o] = fmaf(cc.x, w0r, fmaf(cc.y, w0i, to0[o]));
            to1[o] = fmaf(cc.x, w1r, fmaf(cc.y, w1i, to1[o]));
        }
        if (k < Mn - 1) {
            float nr = w0r * e0r - w0i * e0i, ni = w0r * e0i + w0i * e0r;
            w0r = nr; w0i = ni;
            nr = w1r * e1r - w1i * e1i; ni = w1r * e1i + w1i * e1r;
            w1r = nr; w1i = ni;
        }
    }
#pragma unroll
    for (int c = 0; c < Cn; c++) {
        const float2 hp = *(const float2*)(g_h + ((size_t)(b * Cn + c)) * Sn + s0);
#pragma unroll
        for (int o = 0; o < Cn; o++) {
            const float wv = s_ww[o * Cn + c];
            to0[o] = fmaf(hp.x, wv, to0[o]);
            to1[o] = fmaf(hp.y, wv, to1[o]);
        }
    }
    // layer 3: NO gelu. fc1 -> gelu -> fc2 for both samples.
    const float f2b = fc2b[0];
    float res0 = f2b, res1 = f2b;
#pragma unroll 4
    for (int h4 = 0; h4 < Hn / 4; h4++) {
        const float4 bb = s_fc1b[h4];
        float a0x = bb.x, a0y = bb.y, a0z = bb.z, a0w = bb.w;
        float a1x = bb.x, a1y = bb.y, a1z = bb.z, a1w = bb.w;
#pragma unroll
        for (int c = 0; c < Cn; c++) {
            const float4 w4 = s_fc1[c][h4];
            a0x = fmaf(to0[c], w4.x, a0x);
            a0y = fmaf(to0[c], w4.y, a0y);
            a0z = fmaf(to0[c], w4.z, a0z);
            a0w = fmaf(to0[c], w4.w, a0w);
            a1x = fmaf(to1[c], w4.x, a1x);
            a1y = fmaf(to1[c], w4.y, a1y);
            a1z = fmaf(to1[c], w4.z, a1z);
            a1w = fmaf(to1[c], w4.w, a1w);
        }
        const float4 f2 = s_fc2[h4];
        res0 += gelu_fast(a0x) * f2.x + gelu_fast(a0y) * f2.y
              + gelu_fast(a0z) * f2.z + gelu_fast(a0w) * f2.w;
        res1 += gelu_fast(a1x) * f2.x + gelu_fast(a1y) * f2.y
              + gelu_fast(a1z) * f2.z + gelu_fast(a1w) * f2.w;
    }
    *(float2*)(out + (size_t)b * Sn + s0) = make_float2(res0, res1);
}

// ------------------------------------------------------------------ launch
extern "C" void kernel_launch(void* const* d_in, const int* in_sizes, int n_in,
                              void* d_out, int out_size) {
    const float* x  = (const float*)d_in[0];
    const float* pd = (const float*)d_in[1];
    const float* fc0w = (const float*)d_in[2];
    const float* fc0b = (const float*)d_in[3];
    const float *fc1w, *fc1b, *fc2w, *fc2b;
    const float *sre[4], *sim[4], *lww[4], *lwb[4];

    if (in_sizes[4] == Cn * Hn) {
        fc1w = (const float*)d_in[4]; fc1b = (const float*)d_in[5];
        fc2w = (const float*)d_in[6]; fc2b = (const float*)d_in[7];
        for (int l = 0; l < 4; l++) {
            sre[l] = (const float*)d_in[8 + 4 * l];
            sim[l] = (const float*)d_in[9 + 4 * l];
            lww[l] = (const float*)d_in[10 + 4 * l];
            lwb[l] = (const float*)d_in[11 + 4 * l];
        }
    } else {
        for (int l = 0; l < 4; l++) {
            sre[l] = (const float*)d_in[4 + 4 * l];
            sim[l] = (const float*)d_in[5 + 4 * l];
            lww[l] = (const float*)d_in[6 + 4 * l];
            lwb[l] = (const float*)d_in[7 + 4 * l];
        }
        fc1w = (const float*)d_in[20]; fc1b = (const float*)d_in[21];
        fc2w = (const float*)d_in[22]; fc2b = (const float*)d_in[23];
    }

    float* out = (float*)d_out;

    fno_kmax<<<1, 1024>>>(pd);
    fno_kfc0<<<dim3(Sn / 256, Bn), 256>>>(x, pd, fc0w, fc0b);

    for (int l = 0; l < 3; l++) {
        fno_kfwd<<<dim3(2, Cn, Bn), 256>>>();
        fno_kmix<<<Bn, Cn * Mn>>>(sre[l], sim[l]);
        fno_kinv2<<<dim3(Sn / 512, Bn), 256>>>(lww[l], lwb[l]);
    }
    fno_kfwd<<<dim3(2, Cn, Bn), 256>>>();
    fno_kmix<<<Bn, Cn * Mn>>>(sre[3], sim[3]);
    fno_kfinal2<<<dim3(Sn / 512, Bn), 256>>>(lww[3], lwb[3], fc1w, fc1b, fc2w, fc2b, out);
}